// round 15
// baseline (speedup 1.0000x reference)
#include <cuda_runtime.h>

#define DD   512
#define KK   16
#define TPB  224           // 7 warps; warp owns 64 rows (2/thread), all 16 k
#define RPB  448           // rows per block -> 147 blocks on 148 SMs
#define CH   32            // dims per chunk = 128B per row = one sector
#define NCH  (DD/CH)       // 16 chunks
#define NSTG 3             // pipeline stages (2 chunks in flight)

// ---- dynamic smem layout (bytes) ----
#define SM_CB     0                       // codebook: 32768
#define SM_ZSTG   32768                   // staging: 3 stages * 7 warps * 8192 = 172032
#define SM_SIDX   204800                  // 448 * 4 = 1792
#define SM_SDIST  206592                  // 256 * 4 = 1024 (tree padded)
#define SM_C2S    207616                  // 16 * 4
#define SM_TICKET 207680                  // 4
#define SM_TOTAL  207744

// ---- device scratch (no allocations allowed) ----
__device__ float g_bsum[4096];
__device__ unsigned int g_done = 0;

// ---- packed f32x2 helpers (Blackwell FFMA2) ----
__device__ __forceinline__ void upk2(unsigned long long v, float& lo, float& hi) {
    asm("mov.b64 {%0,%1}, %2;" : "=f"(lo), "=f"(hi) : "l"(v));
}
__device__ __forceinline__ unsigned long long ffma2(unsigned long long a,
                                                    unsigned long long b,
                                                    unsigned long long c) {
    unsigned long long d;
    asm("fma.rn.f32x2 %0, %1, %2, %3;" : "=l"(d) : "l"(a), "l"(b), "l"(c));
    return d;
}
__device__ __forceinline__ void cpasync16(unsigned dst, const void* src) {
    asm volatile("cp.async.cg.shared.global [%0], [%1], 16;" :: "r"(dst), "l"(src) : "memory");
}
#define CP_COMMIT() asm volatile("cp.async.commit_group;" ::: "memory")
#define CP_WAIT(n)  asm volatile("cp.async.wait_group %0;" :: "n"(n) : "memory")

__global__ void __launch_bounds__(TPB, 1) vq_fused(
    const float* __restrict__ z, const float* __restrict__ cb,
    float* __restrict__ zq, float* __restrict__ idxp, float* __restrict__ lossp,
    int nrows, int nblocks, float scale)
{
    extern __shared__ char smem[];
    float*        sc     = (float*)(smem + SM_CB);
    int*          sidx   = (int*)(smem + SM_SIDX);      // [448]
    float*        sdist  = (float*)(smem + SM_SDIST);   // [256], padded for tree
    float*        c2s    = (float*)(smem + SM_C2S);
    unsigned int* ticket = (unsigned int*)(smem + SM_TICKET);

    const int t = threadIdx.x;
    const int w = t >> 5, lane = t & 31;
    const int rowbase = blockIdx.x * RPB;
    const int lastrow = nrows - 1;

    const unsigned smem_sa = (unsigned)__cvta_generic_to_shared(smem);
    // staging for (stage s, warp w): SM_ZSTG + (s*7 + w)*8192
    // inside: row_local*128 + ((piece ^ (row_local&7))<<4)
    const unsigned stg_w = smem_sa + SM_ZSTG + (unsigned)(w * 8192);
    const int swz = lane & 7;                     // read swizzle (same for lane, lane+32)

    // cp.async roles: instr i stages row i*4 + (lane>>3), piece = lane&7
    const int srow = lane >> 3;                   // 0..3
    const int sjj  = lane & 7;                    // 0..7

    // issue chunk c into stage s: 16 cp.async of 16B, full 128B segments per row
    #define ISSUE(c, s) do {                                                        \
        _Pragma("unroll")                                                           \
        for (int i = 0; i < 16; i++) {                                              \
            int rr = i * 4 + srow;                                                  \
            int gr = rowbase + w * 64 + rr; if (gr > lastrow) gr = lastrow;         \
            const char* src = (const char*)z + (size_t)gr * (DD * 4)                \
                              + (size_t)(c) * (CH * 4) + sjj * 16;                  \
            unsigned dst = stg_w + (unsigned)((s) * (7 * 8192))                     \
                           + (unsigned)(rr * 128 + ((sjj ^ (rr & 7)) << 4));        \
            cpasync16(dst, src);                                                    \
        }                                                                           \
        CP_COMMIT();                                                                \
    } while (0)

    // ---- prologue: stage chunks 0,1 ----
    ISSUE(0, 0);
    ISSUE(1, 1);

    // ---- stage codebook (coalesced float4) ----
    for (int i = t; i < KK * DD / 4; i += TPB)
        ((float4*)sc)[i] = ((const float4*)cb)[i];
    __syncthreads();

    // ---- codebook squared norms (identical per-k arithmetic; k strided by 7 warps) ----
    for (int k = w; k < KK; k += 7) {
        float s = 0.f;
        for (int j = lane; j < DD; j += 32) {
            float v = sc[k * DD + j];
            s = fmaf(v, v, s);
        }
        #pragma unroll
        for (int o = 16; o; o >>= 1) s += __shfl_xor_sync(0xffffffffu, s, o);
        if (lane == 0) c2s[k] = s;
    }
    __syncthreads();                      // c2s + sc visible; no block syncs until epilogue

    // ---- accumulators: 16 k x 2 rows, single chain each (R14's exact structure) ----
    unsigned long long acc0[KK], acc1[KK];
    #pragma unroll
    for (int k = 0; k < KK; k++) { acc0[k] = 0ull; acc1[k] = 0ull; }
    unsigned long long z2r0 = 0ull, z2r1 = 0ull;

    const char* stg_rd = (const char*)smem + SM_ZSTG + w * 8192;

    int st = 0;                           // stage of chunk c (c mod 3)
    for (int c = 0; c < NCH; c++) {
        if (c + 2 < NCH) {
            int s2i = st + 2; if (s2i >= NSTG) s2i -= NSTG;
            ISSUE(c + 2, s2i);            // keep 2 chunks in flight
            CP_WAIT(2);                   // chunk c complete
        } else if (c + 1 < NCH) {
            CP_WAIT(1);
        } else {
            CP_WAIT(0);
        }
        __syncwarp();                     // cross-lane staging visibility (warp-local)

        const char* rb0 = stg_rd + st * (7 * 8192) + lane * 128;
        const char* rb1 = rb0 + 32 * 128;
        const float* cbb = sc + c * CH;

        #pragma unroll
        for (int jg = 0; jg < 8; jg++) {  // 8 x 4-dim groups, ascending
            ulonglong2 zv0 = *(const ulonglong2*)(rb0 + ((jg ^ swz) << 4));
            ulonglong2 zv1 = *(const ulonglong2*)(rb1 + ((jg ^ swz) << 4));
            z2r0 = ffma2(zv0.x, zv0.x, z2r0);  z2r0 = ffma2(zv0.y, zv0.y, z2r0);
            z2r1 = ffma2(zv1.x, zv1.x, z2r1);  z2r1 = ffma2(zv1.y, zv1.y, z2r1);
            #pragma unroll
            for (int k = 0; k < KK; k++) {
                // broadcast LDS.128 (same address across lanes), feeds BOTH rows
                ulonglong2 cv = *(const ulonglong2*)(cbb + k * DD + jg * 4);
                acc0[k] = ffma2(zv0.x, cv.x, acc0[k]);
                acc0[k] = ffma2(zv0.y, cv.y, acc0[k]);
                acc1[k] = ffma2(zv1.x, cv.x, acc1[k]);
                acc1[k] = ffma2(zv1.y, cv.y, acc1[k]);
            }
        }
        __syncwarp();                     // all lanes done reading before next overwrite
        if (++st == NSTG) st = 0;
    }

    // ---- argmin with reference-matching quantization (seq k=0..15, strict <) ----
    const int row0 = w * 64 + lane;       // block-local
    const int row1 = row0 + 32;
    float rloss = 0.f;
    {
        float lo, hi;
        upk2(z2r0, lo, hi);
        float z2s = lo + hi;
        float best = 3.4e38f; int bi = 0;
        #pragma unroll
        for (int k = 0; k < KK; k++) {
            upk2(acc0[k], lo, hi);
            float dot = lo + hi;
            float dist = (z2s - 2.0f * dot) + c2s[k];
            if (dist < best) { best = dist; bi = k; }
        }
        const int r = rowbase + row0;
        const bool active = r < nrows;
        if (active) rloss += best;
        sidx[row0] = bi;
        if (active && idxp) idxp[r] = (float)bi;
    }
    {
        float lo, hi;
        upk2(z2r1, lo, hi);
        float z2s = lo + hi;
        float best = 3.4e38f; int bi = 0;
        #pragma unroll
        for (int k = 0; k < KK; k++) {
            upk2(acc1[k], lo, hi);
            float dot = lo + hi;
            float dist = (z2s - 2.0f * dot) + c2s[k];
            if (dist < best) { best = dist; bi = k; }
        }
        const int r = rowbase + row1;
        const bool active = r < nrows;
        if (active) rloss += best;
        sidx[row1] = bi;
        if (active && idxp) idxp[r] = (float)bi;
    }
    sdist[t] = rloss;
    if (t < 256 - TPB) sdist[TPB + t] = 0.f;   // pad tree slots 224..255
    __syncthreads();

    // ---- cooperative coalesced z_q write: flat index over rows x 128 float4 ----
    float4* zqg = (float4*)zq;
    const int rmax = min(RPB, nrows - rowbase);
    const int ftot = rmax * 128;
    for (int f = t; f < ftot; f += TPB) {
        int row = f >> 7;
        int col = f & 127;
        int b = sidx[row];                                  // broadcast (<=2 rows/warp)
        float4 cv = *(const float4*)(sc + b * DD + col * 4);
        zqg[(size_t)(rowbase + row) * (DD / 4) + col] = cv; // coalesced STG.128
    }

    // ---- deterministic block loss partial (tree over 256 padded slots) ----
    #pragma unroll
    for (int s2 = 128; s2 > 0; s2 >>= 1) {
        if (t < s2) sdist[t] += sdist[t + s2];
        __syncthreads();
    }
    if (t == 0) g_bsum[blockIdx.x] = sdist[0];

    // ---- last-block finalize (deterministic order; counter reset for graph replay) ----
    if (t == 0) {
        __threadfence();
        ticket[0] = atomicAdd(&g_done, 1u);
    }
    __syncthreads();
    if (ticket[0] == (unsigned)(nblocks - 1)) {
        float s = 0.f;
        for (int i = t; i < nblocks; i += TPB) s += __ldcg(&g_bsum[i]);
        sdist[t] = s;
        if (t < 256 - TPB) sdist[TPB + t] = 0.f;
        __syncthreads();
        #pragma unroll
        for (int s2 = 128; s2 > 0; s2 >>= 1) {
            if (t < s2) sdist[t] += sdist[t + s2];
            __syncthreads();
        }
        if (t == 0) {
            if (lossp) lossp[0] = sdist[0] * scale;
            g_done = 0;
        }
    }
    #undef ISSUE
}

extern "C" void kernel_launch(void* const* d_in, const int* in_sizes, int n_in,
                              void* d_out, int out_size) {
    const float* z  = (const float*)d_in[0];
    const float* cb = (const float*)d_in[1];
    int zn = in_sizes[0];          // N * D
    int N  = zn / DD;

    float* zq = (float*)d_out;
    int has_idx  = (out_size >= zn + N) ? 1 : 0;
    float* idxp  = has_idx ? ((float*)d_out + zn) : nullptr;
    float* lossp = (out_size >= zn + N + 1) ? ((float*)d_out + zn + N) : nullptr;

    int nb = (N + RPB - 1) / RPB;
    float scale = 1.25f / ((float)N * (float)DD);

    cudaFuncSetAttribute(vq_fused, cudaFuncAttributeMaxDynamicSharedMemorySize, SM_TOTAL);
    vq_fused<<<nb, TPB, SM_TOTAL>>>(z, cb, zq, idxp, lossp, N, nb, scale);
}

// round 16
// speedup vs baseline: 1.0518x; 1.0518x over previous
#include <cuda_runtime.h>

#define DD   512
#define KK   16
#define TPB  128           // 4 warps; warp owns 64 rows (2/thread), all 16 k
#define RPB  256           // rows per block -> grid 256 = 2 blocks/SM on 128 SMs
#define CH   32            // dims per chunk = 128B per row = one sector
#define NCH  (DD/CH)       // 16 chunks

// ---- dynamic smem layout (bytes) ----
#define SM_CB     0                       // codebook: 32768
#define SM_ZSTG   32768                   // staging: 2 stages * 4 warps * 8192 = 65536
#define SM_SIDX   98304                   // 256 * 4 = 1024
#define SM_SDIST  99328                   // 128 * 4 = 512
#define SM_C2S    99840                   // 16 * 4
#define SM_TICKET 99904                   // 4
#define SM_TOTAL  99968

// ---- device scratch (no allocations allowed) ----
__device__ float g_bsum[4096];
__device__ unsigned int g_done = 0;

// ---- packed f32x2 helpers (Blackwell FFMA2) ----
__device__ __forceinline__ void upk2(unsigned long long v, float& lo, float& hi) {
    asm("mov.b64 {%0,%1}, %2;" : "=f"(lo), "=f"(hi) : "l"(v));
}
__device__ __forceinline__ unsigned long long ffma2(unsigned long long a,
                                                    unsigned long long b,
                                                    unsigned long long c) {
    unsigned long long d;
    asm("fma.rn.f32x2 %0, %1, %2, %3;" : "=l"(d) : "l"(a), "l"(b), "l"(c));
    return d;
}
__device__ __forceinline__ void cpasync16(unsigned dst, const void* src) {
    asm volatile("cp.async.cg.shared.global [%0], [%1], 16;" :: "r"(dst), "l"(src) : "memory");
}
#define CP_COMMIT() asm volatile("cp.async.commit_group;" ::: "memory")
#define CP_WAIT(n)  asm volatile("cp.async.wait_group %0;" :: "n"(n) : "memory")

__global__ void __launch_bounds__(TPB, 2) vq_fused(
    const float* __restrict__ z, const float* __restrict__ cb,
    float* __restrict__ zq, float* __restrict__ idxp, float* __restrict__ lossp,
    int nrows, int nblocks, float scale)
{
    extern __shared__ char smem[];
    float*        sc     = (float*)(smem + SM_CB);
    int*          sidx   = (int*)(smem + SM_SIDX);      // [256]
    float*        sdist  = (float*)(smem + SM_SDIST);   // [128] per-thread loss
    float*        c2s    = (float*)(smem + SM_C2S);
    unsigned int* ticket = (unsigned int*)(smem + SM_TICKET);

    const int t = threadIdx.x;
    const int w = t >> 5, lane = t & 31;
    const int rowbase = blockIdx.x * RPB;
    const int lastrow = nrows - 1;

    const unsigned smem_sa = (unsigned)__cvta_generic_to_shared(smem);
    // staging for (stage s, warp w): SM_ZSTG + (s*4 + w)*8192
    // inside: row_local*128 + ((piece ^ (row_local&7))<<4)   (R14 swizzle)
    const unsigned stg_w = smem_sa + SM_ZSTG + (unsigned)(w * 8192);
    const int swz = lane & 7;                     // read swizzle (same for lane, lane+32)

    // cp.async roles: instr i stages row i*4 + (lane>>3), piece = lane&7
    const int srow = lane >> 3;                   // 0..3
    const int sjj  = lane & 7;                    // 0..7

    // issue chunk c into stage s: 16 cp.async of 16B, full 128B segments per row
    #define ISSUE(c, s) do {                                                        \
        _Pragma("unroll")                                                           \
        for (int i = 0; i < 16; i++) {                                              \
            int rr = i * 4 + srow;                                                  \
            int gr = rowbase + w * 64 + rr; if (gr > lastrow) gr = lastrow;         \
            const char* src = (const char*)z + (size_t)gr * (DD * 4)                \
                              + (size_t)(c) * (CH * 4) + sjj * 16;                  \
            unsigned dst = stg_w + (unsigned)((s) * (4 * 8192))                     \
                           + (unsigned)(rr * 128 + ((sjj ^ (rr & 7)) << 4));        \
            cpasync16(dst, src);                                                    \
        }                                                                           \
        CP_COMMIT();                                                                \
    } while (0)

    // ---- prologue: stage chunk 0 ----
    ISSUE(0, 0);

    // ---- stage codebook (coalesced float4) ----
    for (int i = t; i < KK * DD / 4; i += TPB)
        ((float4*)sc)[i] = ((const float4*)cb)[i];
    __syncthreads();

    // ---- codebook squared norms (identical per-k arithmetic; k strided by 4 warps) ----
    for (int k = w; k < KK; k += 4) {
        float s = 0.f;
        for (int j = lane; j < DD; j += 32) {
            float v = sc[k * DD + j];
            s = fmaf(v, v, s);
        }
        #pragma unroll
        for (int o = 16; o; o >>= 1) s += __shfl_xor_sync(0xffffffffu, s, o);
        if (lane == 0) c2s[k] = s;
    }
    __syncthreads();                      // c2s + sc visible; no block syncs until epilogue

    // ---- accumulators: 16 k x 2 rows, single chain each (R14's exact structure) ----
    unsigned long long acc0[KK], acc1[KK];
    #pragma unroll
    for (int k = 0; k < KK; k++) { acc0[k] = 0ull; acc1[k] = 0ull; }
    unsigned long long z2r0 = 0ull, z2r1 = 0ull;

    const char* stg_rd = (const char*)smem + SM_ZSTG + w * 8192;

    for (int c = 0; c < NCH; c++) {
        if (c + 1 < NCH) {
            ISSUE(c + 1, (c + 1) & 1);    // overlaps chunk c wait + compute
            CP_WAIT(1);                   // chunk c complete, c+1 in flight
        } else {
            CP_WAIT(0);
        }
        __syncwarp();                     // cross-lane staging visibility (warp-local)

        const char* rb0 = stg_rd + (c & 1) * (4 * 8192) + lane * 128;
        const char* rb1 = rb0 + 32 * 128;
        const float* cbb = sc + c * CH;

        #pragma unroll
        for (int jg = 0; jg < 8; jg++) {  // 8 x 4-dim groups, ascending
            ulonglong2 zv0 = *(const ulonglong2*)(rb0 + ((jg ^ swz) << 4));
            ulonglong2 zv1 = *(const ulonglong2*)(rb1 + ((jg ^ swz) << 4));
            z2r0 = ffma2(zv0.x, zv0.x, z2r0);  z2r0 = ffma2(zv0.y, zv0.y, z2r0);
            z2r1 = ffma2(zv1.x, zv1.x, z2r1);  z2r1 = ffma2(zv1.y, zv1.y, z2r1);
            #pragma unroll
            for (int k = 0; k < KK; k++) {
                // broadcast LDS.128 (same address across lanes), feeds BOTH rows
                ulonglong2 cv = *(const ulonglong2*)(cbb + k * DD + jg * 4);
                acc0[k] = ffma2(zv0.x, cv.x, acc0[k]);
                acc0[k] = ffma2(zv0.y, cv.y, acc0[k]);
                acc1[k] = ffma2(zv1.x, cv.x, acc1[k]);
                acc1[k] = ffma2(zv1.y, cv.y, acc1[k]);
            }
        }
        __syncwarp();                     // all lanes done reading before next overwrite
    }

    // ---- argmin with reference-matching quantization (seq k=0..15, strict <) ----
    const int row0 = w * 64 + lane;       // block-local
    const int row1 = row0 + 32;
    float rloss = 0.f;
    {
        float lo, hi;
        upk2(z2r0, lo, hi);
        float z2s = lo + hi;
        float best = 3.4e38f; int bi = 0;
        #pragma unroll
        for (int k = 0; k < KK; k++) {
            upk2(acc0[k], lo, hi);
            float dot = lo + hi;
            float dist = (z2s - 2.0f * dot) + c2s[k];
            if (dist < best) { best = dist; bi = k; }
        }
        const int r = rowbase + row0;
        const bool active = r < nrows;
        if (active) rloss += best;
        sidx[row0] = bi;
        if (active && idxp) idxp[r] = (float)bi;
    }
    {
        float lo, hi;
        upk2(z2r1, lo, hi);
        float z2s = lo + hi;
        float best = 3.4e38f; int bi = 0;
        #pragma unroll
        for (int k = 0; k < KK; k++) {
            upk2(acc1[k], lo, hi);
            float dot = lo + hi;
            float dist = (z2s - 2.0f * dot) + c2s[k];
            if (dist < best) { best = dist; bi = k; }
        }
        const int r = rowbase + row1;
        const bool active = r < nrows;
        if (active) rloss += best;
        sidx[row1] = bi;
        if (active && idxp) idxp[r] = (float)bi;
    }
    sdist[t] = rloss;
    __syncthreads();

    // ---- cooperative coalesced z_q write: flat index over rows x 128 float4 ----
    float4* zqg = (float4*)zq;
    const int rmax = min(RPB, nrows - rowbase);
    const int ftot = rmax * 128;
    for (int f = t; f < ftot; f += TPB) {
        int row = f >> 7;
        int col = f & 127;
        int b = sidx[row];                                  // broadcast (1 row/warp-pass)
        float4 cv = *(const float4*)(sc + b * DD + col * 4);
        zqg[(size_t)(rowbase + row) * (DD / 4) + col] = cv; // coalesced STG.128
    }

    // ---- deterministic block loss partial (tree over 128) ----
    #pragma unroll
    for (int s2 = 64; s2 > 0; s2 >>= 1) {
        if (t < s2) sdist[t] += sdist[t + s2];
        __syncthreads();
    }
    if (t == 0) g_bsum[blockIdx.x] = sdist[0];

    // ---- last-block finalize (deterministic order; counter reset for graph replay) ----
    if (t == 0) {
        __threadfence();
        ticket[0] = atomicAdd(&g_done, 1u);
    }
    __syncthreads();
    if (ticket[0] == (unsigned)(nblocks - 1)) {
        float s = 0.f;
        for (int i = t; i < nblocks; i += TPB) s += __ldcg(&g_bsum[i]);
        sdist[t] = s;
        __syncthreads();
        #pragma unroll
        for (int s2 = 64; s2 > 0; s2 >>= 1) {
            if (t < s2) sdist[t] += sdist[t + s2];
            __syncthreads();
        }
        if (t == 0) {
            if (lossp) lossp[0] = sdist[0] * scale;
            g_done = 0;
        }
    }
    #undef ISSUE
}

extern "C" void kernel_launch(void* const* d_in, const int* in_sizes, int n_in,
                              void* d_out, int out_size) {
    const float* z  = (const float*)d_in[0];
    const float* cb = (const float*)d_in[1];
    int zn = in_sizes[0];          // N * D
    int N  = zn / DD;

    float* zq = (float*)d_out;
    int has_idx  = (out_size >= zn + N) ? 1 : 0;
    float* idxp  = has_idx ? ((float*)d_out + zn) : nullptr;
    float* lossp = (out_size >= zn + N + 1) ? ((float*)d_out + zn + N) : nullptr;

    int nb = (N + RPB - 1) / RPB;
    float scale = 1.25f / ((float)N * (float)DD);

    cudaFuncSetAttribute(vq_fused, cudaFuncAttributeMaxDynamicSharedMemorySize, SM_TOTAL);
    vq_fused<<<nb, TPB, SM_TOTAL>>>(z, cb, zq, idxp, lossp, N, nb, scale);
}

// round 17
// speedup vs baseline: 1.0801x; 1.0269x over previous
#include <cuda_runtime.h>

#define DD   512
#define KK   16
#define TPB  256           // 8 warps; warp owns 64 rows (2/thread), all 16 k
#define RPB  512           // rows per block -> grid 128 = 1 block/SM
#define CH   32            // dims per chunk = 128B per row = one sector
#define NCH  (DD/CH)       // 16 chunks

// ---- dynamic smem layout (bytes) ----
#define SM_CB     0                       // codebook: 32768
#define SM_ZSTG   32768                   // staging: 2 stages * 8 warps * 8192 = 131072
#define SM_SWARP  163840                  // 8 * 4
#define SM_SFIN   163872                  // 256 * 4 (finalize tree)
#define SM_C2S    164896                  // 16 * 4
#define SM_TICKET 164960                  // 4
#define SM_TOTAL  165000

// ---- device scratch (no allocations allowed) ----
__device__ float g_bsum[4096];
__device__ unsigned int g_done = 0;

// ---- packed f32x2 helpers (Blackwell FFMA2) ----
__device__ __forceinline__ void upk2(unsigned long long v, float& lo, float& hi) {
    asm("mov.b64 {%0,%1}, %2;" : "=f"(lo), "=f"(hi) : "l"(v));
}
__device__ __forceinline__ unsigned long long ffma2(unsigned long long a,
                                                    unsigned long long b,
                                                    unsigned long long c) {
    unsigned long long d;
    asm("fma.rn.f32x2 %0, %1, %2, %3;" : "=l"(d) : "l"(a), "l"(b), "l"(c));
    return d;
}
__device__ __forceinline__ void cpasync16(unsigned dst, const void* src) {
    asm volatile("cp.async.cg.shared.global [%0], [%1], 16;" :: "r"(dst), "l"(src) : "memory");
}
#define CP_COMMIT() asm volatile("cp.async.commit_group;" ::: "memory")
#define CP_WAIT(n)  asm volatile("cp.async.wait_group %0;" :: "n"(n) : "memory")

__global__ void __launch_bounds__(TPB, 1) vq_fused(
    const float* __restrict__ z, const float* __restrict__ cb,
    float* __restrict__ zq, float* __restrict__ idxp, float* __restrict__ lossp,
    int nrows, int nblocks, float scale)
{
    extern __shared__ char smem[];
    float*        sc     = (float*)(smem + SM_CB);
    float*        swarp  = (float*)(smem + SM_SWARP);   // [8] per-warp loss
    float*        sfin   = (float*)(smem + SM_SFIN);    // [256] finalize tree
    float*        c2s    = (float*)(smem + SM_C2S);
    unsigned int* ticket = (unsigned int*)(smem + SM_TICKET);

    const int t = threadIdx.x;
    const int w = t >> 5, lane = t & 31;
    const int rowbase = blockIdx.x * RPB;
    const int lastrow = nrows - 1;

    const unsigned smem_sa = (unsigned)__cvta_generic_to_shared(smem);
    // staging for (stage s, warp w): SM_ZSTG + (s*8 + w)*8192
    // inside: row_local*128 + ((piece ^ (row_local&7))<<4)
    const unsigned stg_w = smem_sa + SM_ZSTG + (unsigned)(w * 8192);
    const int swz = lane & 7;                     // read swizzle (same for lane, lane+32)

    // cp.async roles: instr i stages row i*4 + (lane>>3), piece = lane&7
    const int srow = lane >> 3;                   // 0..3
    const int sjj  = lane & 7;                    // 0..7

    // issue chunk c into stage s: 16 cp.async of 16B, full 128B segments per row
    #define ISSUE(c, s) do {                                                        \
        _Pragma("unroll")                                                           \
        for (int i = 0; i < 16; i++) {                                              \
            int rr = i * 4 + srow;                                                  \
            int gr = rowbase + w * 64 + rr; if (gr > lastrow) gr = lastrow;         \
            const char* src = (const char*)z + (size_t)gr * (DD * 4)                \
                              + (size_t)(c) * (CH * 4) + sjj * 16;                  \
            unsigned dst = stg_w + (unsigned)((s) * 65536)                          \
                           + (unsigned)(rr * 128 + ((sjj ^ (rr & 7)) << 4));        \
            cpasync16(dst, src);                                                    \
        }                                                                           \
        CP_COMMIT();                                                                \
    } while (0)

    // ---- prologue: stage chunk 0 ----
    ISSUE(0, 0);

    // ---- stage codebook (coalesced float4) ----
    for (int i = t; i < KK * DD / 4; i += TPB)
        ((float4*)sc)[i] = ((const float4*)cb)[i];
    __syncthreads();

    // ---- codebook squared norms (identical per-k arithmetic as before) ----
    #pragma unroll
    for (int kk = 0; kk < 2; kk++) {
        int k = w * 2 + kk;
        float s = 0.f;
        for (int j = lane; j < DD; j += 32) {
            float v = sc[k * DD + j];
            s = fmaf(v, v, s);
        }
        #pragma unroll
        for (int o = 16; o; o >>= 1) s += __shfl_xor_sync(0xffffffffu, s, o);
        if (lane == 0) c2s[k] = s;
    }
    __syncthreads();                      // c2s + sc visible; NO more block syncs until loss

    // ---- accumulators: 16 k x 2 rows, single chain each (R14's exact structure) ----
    unsigned long long acc0[KK], acc1[KK];
    #pragma unroll
    for (int k = 0; k < KK; k++) { acc0[k] = 0ull; acc1[k] = 0ull; }
    unsigned long long z2r0 = 0ull, z2r1 = 0ull;

    const char* stg_rd = (const char*)smem + SM_ZSTG + w * 8192;

    for (int c = 0; c < NCH; c++) {
        if (c + 1 < NCH) {
            ISSUE(c + 1, (c + 1) & 1);    // overlaps chunk c wait + compute
            CP_WAIT(1);                   // chunk c complete, c+1 in flight
        } else {
            CP_WAIT(0);
        }
        __syncwarp();                     // cross-lane staging visibility (warp-local)

        const char* rb0 = stg_rd + (c & 1) * 65536 + lane * 128;
        const char* rb1 = rb0 + 32 * 128;
        const float* cbb = sc + c * CH;

        #pragma unroll
        for (int jg = 0; jg < 8; jg++) {  // 8 x 4-dim groups, ascending
            ulonglong2 zv0 = *(const ulonglong2*)(rb0 + ((jg ^ swz) << 4));
            ulonglong2 zv1 = *(const ulonglong2*)(rb1 + ((jg ^ swz) << 4));
            z2r0 = ffma2(zv0.x, zv0.x, z2r0);  z2r0 = ffma2(zv0.y, zv0.y, z2r0);
            z2r1 = ffma2(zv1.x, zv1.x, z2r1);  z2r1 = ffma2(zv1.y, zv1.y, z2r1);
            #pragma unroll
            for (int k = 0; k < KK; k++) {
                // broadcast LDS.128 (same address across lanes), feeds BOTH rows
                ulonglong2 cv = *(const ulonglong2*)(cbb + k * DD + jg * 4);
                acc0[k] = ffma2(zv0.x, cv.x, acc0[k]);
                acc0[k] = ffma2(zv0.y, cv.y, acc0[k]);
                acc1[k] = ffma2(zv1.x, cv.x, acc1[k]);
                acc1[k] = ffma2(zv1.y, cv.y, acc1[k]);
            }
        }
        __syncwarp();                     // all lanes done reading before next overwrite
    }

    // ---- argmin with reference-matching quantization (seq k=0..15, strict <) ----
    const int row0 = w * 64 + lane;       // block-local
    const int row1 = row0 + 32;
    float rloss = 0.f;
    int bi0 = 0, bi1 = 0;
    {
        float lo, hi;
        upk2(z2r0, lo, hi);
        float z2s = lo + hi;
        float best = 3.4e38f;
        #pragma unroll
        for (int k = 0; k < KK; k++) {
            upk2(acc0[k], lo, hi);
            float dot = lo + hi;
            float dist = (z2s - 2.0f * dot) + c2s[k];
            if (dist < best) { best = dist; bi0 = k; }
        }
        const int r = rowbase + row0;
        const bool active = r < nrows;
        if (active) rloss += best;
        if (active && idxp) idxp[r] = (float)bi0;
    }
    {
        float lo, hi;
        upk2(z2r1, lo, hi);
        float z2s = lo + hi;
        float best = 3.4e38f;
        #pragma unroll
        for (int k = 0; k < KK; k++) {
            upk2(acc1[k], lo, hi);
            float dot = lo + hi;
            float dist = (z2s - 2.0f * dot) + c2s[k];
            if (dist < best) { best = dist; bi1 = k; }
        }
        const int r = rowbase + row1;
        const bool active = r < nrows;
        if (active) rloss += best;
        if (active && idxp) idxp[r] = (float)bi1;
    }

    // ---- WARP-LOCAL z_q write: starts the moment THIS warp's mainloop ends ----
    // (no block barrier; overlaps sibling warps' mainloop compute/reads)
    {
        float4* zqg = (float4*)zq;
        const float4* scf4 = (const float4*)sc;
        #pragma unroll 4
        for (int rr = 0; rr < 64; rr++) {
            int b = __shfl_sync(0xffffffffu, (rr < 32) ? bi0 : bi1, rr & 31);
            int grow = rowbase + w * 64 + rr;
            if (grow < nrows) {
                const float4* crow = scf4 + b * (DD / 4);
                float4* orow = zqg + (size_t)grow * (DD / 4);
                #pragma unroll
                for (int i = 0; i < 4; i++)
                    orow[lane + 32 * i] = crow[lane + 32 * i];  // LDS conflict-free + STG.128 coalesced
            }
        }
    }

    // ---- loss: warp shfl-reduce (deterministic), then serial 8-way sum ----
    #pragma unroll
    for (int o = 16; o; o >>= 1) rloss += __shfl_down_sync(0xffffffffu, rloss, o);
    if (lane == 0) swarp[w] = rloss;
    __syncthreads();
    if (t == 0) {
        float s = 0.f;
        #pragma unroll
        for (int i = 0; i < 8; i++) s += swarp[i];
        g_bsum[blockIdx.x] = s;
    }

    // ---- last-block finalize (deterministic order; counter reset for graph replay) ----
    if (t == 0) {
        __threadfence();
        ticket[0] = atomicAdd(&g_done, 1u);
    }
    __syncthreads();
    if (ticket[0] == (unsigned)(nblocks - 1)) {
        float s = 0.f;
        for (int i = t; i < nblocks; i += TPB) s += __ldcg(&g_bsum[i]);
        sfin[t] = s;
        __syncthreads();
        #pragma unroll
        for (int s2 = 128; s2 > 0; s2 >>= 1) {
            if (t < s2) sfin[t] += sfin[t + s2];
            __syncthreads();
        }
        if (t == 0) {
            if (lossp) lossp[0] = sfin[0] * scale;
            g_done = 0;
        }
    }
    #undef ISSUE
}

extern "C" void kernel_launch(void* const* d_in, const int* in_sizes, int n_in,
                              void* d_out, int out_size) {
    const float* z  = (const float*)d_in[0];
    const float* cb = (const float*)d_in[1];
    int zn = in_sizes[0];          // N * D
    int N  = zn / DD;

    float* zq = (float*)d_out;
    int has_idx  = (out_size >= zn + N) ? 1 : 0;
    float* idxp  = has_idx ? ((float*)d_out + zn) : nullptr;
    float* lossp = (out_size >= zn + N + 1) ? ((float*)d_out + zn + N) : nullptr;

    int nb = (N + RPB - 1) / RPB;
    float scale = 1.25f / ((float)N * (float)DD);

    cudaFuncSetAttribute(vq_fused, cudaFuncAttributeMaxDynamicSharedMemorySize, SM_TOTAL);
    vq_fused<<<nb, TPB, SM_TOTAL>>>(z, cb, zq, idxp, lossp, N, nb, scale);
}